// round 2
// baseline (speedup 1.0000x reference)
#include <cuda_runtime.h>

#define D_MODEL 1024
#define NHEADS  16
#define HD      64
#define BATCH   4
#define SEQ     2048
#define MTOT    (BATCH*SEQ)   // 8192

// Scratch (no cudaMalloc allowed): q/k/v in [b,h,s,hd], ctx in [b,s,D]
__device__ float g_q[MTOT*D_MODEL];
__device__ float g_k[MTOT*D_MODEL];
__device__ float g_v[MTOT*D_MODEL];
__device__ float g_ctx[MTOT*D_MODEL];

// ---------------------------------------------------------------------------
// fp32 GEMM core: C[128x128] tile, K-step 8, 256 threads, 8x8 per thread.
// A [M,K] row-major, B [K,N] row-major. FMA-bound by design.
// ---------------------------------------------------------------------------
__device__ __forceinline__ void gemm_core(const float* __restrict__ A,
                                          const float* __restrict__ B,
                                          float acc[8][8])
{
    __shared__ float sA[8][132];   // transposed: sA[k][m] (pad kills store conflicts)
    __shared__ float sB[8][128];   // sB[k][n]

    const int tid = threadIdx.x;
    const int tx  = tid & 15, ty = tid >> 4;
    const int m0  = blockIdx.y * 128;
    const int n0  = blockIdx.x * 128;

    const int arow = tid >> 1;          // 0..127
    const int akk  = (tid & 1) * 4;     // 0 or 4
    const int bkk  = tid >> 5;          // 0..7
    const int bcol = (tid & 31) * 4;    // 0..124

    const float* Ap = A + (size_t)(m0 + arow) * D_MODEL + akk;
    const float* Bp = B + (size_t)bkk * D_MODEL + n0 + bcol;

    #pragma unroll
    for (int i = 0; i < 8; i++)
        #pragma unroll
        for (int j = 0; j < 8; j++) acc[i][j] = 0.f;

    for (int k0 = 0; k0 < D_MODEL; k0 += 8) {
        float4 a4 = *(const float4*)(Ap + k0);
        float4 b4 = *(const float4*)(Bp + (size_t)k0 * D_MODEL);
        __syncthreads();
        sA[akk + 0][arow] = a4.x;
        sA[akk + 1][arow] = a4.y;
        sA[akk + 2][arow] = a4.z;
        sA[akk + 3][arow] = a4.w;
        *(float4*)&sB[bkk][bcol] = b4;
        __syncthreads();

        #pragma unroll
        for (int kk = 0; kk < 8; kk++) {
            float a[8], b[8];
            *(float4*)&a[0] = *(const float4*)&sA[kk][ty * 8];
            *(float4*)&a[4] = *(const float4*)&sA[kk][ty * 8 + 4];
            *(float4*)&b[0] = *(const float4*)&sB[kk][tx * 8];
            *(float4*)&b[4] = *(const float4*)&sB[kk][tx * 8 + 4];
            #pragma unroll
            for (int i = 0; i < 8; i++)
                #pragma unroll
                for (int j = 0; j < 8; j++)
                    acc[i][j] = fmaf(a[i], b[j], acc[i][j]);
        }
    }
}

// ---------------------------------------------------------------------------
// QKV projection: z = 0/1/2 selects W and destination; output scattered to
// [b,h,s,hd] so attention reads are contiguous.
// ---------------------------------------------------------------------------
__global__ __launch_bounds__(256) void gemm_qkv_kernel(
    const float* __restrict__ X,
    const float* __restrict__ Wq,
    const float* __restrict__ Wk,
    const float* __restrict__ Wv)
{
    const float* W;
    float* Out;
    if (blockIdx.z == 0)      { W = Wq; Out = g_q; }
    else if (blockIdx.z == 1) { W = Wk; Out = g_k; }
    else                      { W = Wv; Out = g_v; }

    float acc[8][8];
    gemm_core(X, W, acc);

    const int tid = threadIdx.x;
    const int tx  = tid & 15, ty = tid >> 4;
    const int m0  = blockIdx.y * 128, n0 = blockIdx.x * 128;

    #pragma unroll
    for (int i = 0; i < 8; i++) {
        int m = m0 + ty * 8 + i;
        int b = m >> 11;          // SEQ = 2048
        int s = m & (SEQ - 1);
        #pragma unroll
        for (int j = 0; j < 8; j++) {
            int n  = n0 + tx * 8 + j;
            int h  = n >> 6;
            int hd = n & 63;
            Out[(((size_t)(b * NHEADS + h) * SEQ) + s) * HD + hd] = acc[i][j];
        }
    }
}

// ---------------------------------------------------------------------------
// Output projection: out = ctx @ Wo + bo
// ---------------------------------------------------------------------------
__global__ __launch_bounds__(256) void gemm_out_kernel(
    const float* __restrict__ Wo,
    const float* __restrict__ bo,
    float* __restrict__ out)
{
    float acc[8][8];
    gemm_core(g_ctx, Wo, acc);

    const int tid = threadIdx.x;
    const int tx  = tid & 15, ty = tid >> 4;
    const int m0  = blockIdx.y * 128, n0 = blockIdx.x * 128;

    #pragma unroll
    for (int i = 0; i < 8; i++) {
        int m = m0 + ty * 8 + i;
        #pragma unroll
        for (int j = 0; j < 8; j += 4) {
            int n = n0 + tx * 8 + j;
            float4 r;
            r.x = acc[i][j + 0] + bo[n + 0];
            r.y = acc[i][j + 1] + bo[n + 1];
            r.z = acc[i][j + 2] + bo[n + 2];
            r.w = acc[i][j + 3] + bo[n + 3];
            *(float4*)&out[(size_t)m * D_MODEL + n] = r;
        }
    }
}

// ---------------------------------------------------------------------------
// Flash attention, fp32, causal. Block: 64 queries x (one b,h). 256 threads,
// 4x4 microtiles on a 16x16 thread grid. KV tiles of 64, diagonal masked,
// tiles beyond the diagonal skipped entirely.
// smem: sQt[d][m], sKt[d][n], sV[k][d], sP[m][n]  (each 64x68 floats)
// ---------------------------------------------------------------------------
#define ATTN_SMEM (4 * 64 * 68 * 4)

__global__ __launch_bounds__(256) void attn_kernel()
{
    extern __shared__ float sm[];
    float* sQt = sm;                // [64][68]  d-major Q (pre-scaled)
    float* sKt = sm + 64 * 68;      // [64][68]  d-major K
    float* sV  = sm + 2 * 64 * 68;  // [64][68]  k-major V
    float* sP  = sm + 3 * 64 * 68;  // [64][68]  row-major P

    const int tid = threadIdx.x;
    const int tx  = tid & 15, ty = tid >> 4;
    const int bh  = blockIdx.y;     // b*16 + h
    const int qt  = blockIdx.x;
    const int q0  = qt * 64;

    const float* Qg = g_q + (size_t)bh * SEQ * HD;
    const float* Kg = g_k + (size_t)bh * SEQ * HD;
    const float* Vg = g_v + (size_t)bh * SEQ * HD;

    // Q tile -> sQt (transposed, scaled by 1/sqrt(64) = 0.125)
    {
        const int row = tid >> 2;            // 0..63
        const int dg  = (tid & 3) * 16;      // 0,16,32,48
        const float* src = Qg + (size_t)(q0 + row) * HD + dg;
        #pragma unroll
        for (int v = 0; v < 4; v++) {
            float4 t = *(const float4*)(src + v * 4);
            sQt[(dg + v * 4 + 0) * 68 + row] = t.x * 0.125f;
            sQt[(dg + v * 4 + 1) * 68 + row] = t.y * 0.125f;
            sQt[(dg + v * 4 + 2) * 68 + row] = t.z * 0.125f;
            sQt[(dg + v * 4 + 3) * 68 + row] = t.w * 0.125f;
        }
    }

    float accO[4][4];
    float m_run[4], l_run[4];
    #pragma unroll
    for (int i = 0; i < 4; i++) {
        m_run[i] = -1e30f;
        l_run[i] = 0.f;
        #pragma unroll
        for (int j = 0; j < 4; j++) accO[i][j] = 0.f;
    }

    for (int t = 0; t <= qt; t++) {
        const int k0 = t * 64;
        __syncthreads();   // previous tile fully consumed; also fences the Q fill

        // K (transposed) + V tiles
        {
            const int row = tid >> 2;
            const int dg  = (tid & 3) * 16;
            const float* ks = Kg + (size_t)(k0 + row) * HD + dg;
            const float* vs = Vg + (size_t)(k0 + row) * HD + dg;
            #pragma unroll
            for (int v = 0; v < 4; v++) {
                float4 tk = *(const float4*)(ks + v * 4);
                sKt[(dg + v * 4 + 0) * 68 + row] = tk.x;
                sKt[(dg + v * 4 + 1) * 68 + row] = tk.y;
                sKt[(dg + v * 4 + 2) * 68 + row] = tk.z;
                sKt[(dg + v * 4 + 3) * 68 + row] = tk.w;
                *(float4*)&sV[row * 68 + dg + v * 4] = *(const float4*)(vs + v * 4);
            }
        }
        __syncthreads();

        // S = (Q*scale) @ K^T  (4x4 per thread)
        float sc[4][4];
        #pragma unroll
        for (int i = 0; i < 4; i++)
            #pragma unroll
            for (int j = 0; j < 4; j++) sc[i][j] = 0.f;

        #pragma unroll 16
        for (int d = 0; d < 64; d++) {
            float a[4], b[4];
            *(float4*)a = *(const float4*)&sQt[d * 68 + ty * 4];
            *(float4*)b = *(const float4*)&sKt[d * 68 + tx * 4];
            #pragma unroll
            for (int i = 0; i < 4; i++)
                #pragma unroll
                for (int j = 0; j < 4; j++)
                    sc[i][j] = fmaf(a[i], b[j], sc[i][j]);
        }

        // causal mask on the diagonal tile
        if (t == qt) {
            #pragma unroll
            for (int i = 0; i < 4; i++)
                #pragma unroll
                for (int j = 0; j < 4; j++)
                    if (tx * 4 + j > ty * 4 + i) sc[i][j] = -1e30f;
        }

        // online softmax (row stats replicated across the 16-lane row group)
        #pragma unroll
        for (int i = 0; i < 4; i++) {
            float tm = fmaxf(fmaxf(sc[i][0], sc[i][1]), fmaxf(sc[i][2], sc[i][3]));
            tm = fmaxf(tm, __shfl_xor_sync(0xffffffffu, tm, 1, 16));
            tm = fmaxf(tm, __shfl_xor_sync(0xffffffffu, tm, 2, 16));
            tm = fmaxf(tm, __shfl_xor_sync(0xffffffffu, tm, 4, 16));
            tm = fmaxf(tm, __shfl_xor_sync(0xffffffffu, tm, 8, 16));

            float mnew   = fmaxf(m_run[i], tm);
            float sc_old = __expf(m_run[i] - mnew);
            m_run[i] = mnew;

            float tsum = 0.f;
            #pragma unroll
            for (int j = 0; j < 4; j++) {
                float p = __expf(sc[i][j] - mnew);
                sc[i][j] = p;
                tsum += p;
            }
            tsum += __shfl_xor_sync(0xffffffffu, tsum, 1, 16);
            tsum += __shfl_xor_sync(0xffffffffu, tsum, 2, 16);
            tsum += __shfl_xor_sync(0xffffffffu, tsum, 4, 16);
            tsum += __shfl_xor_sync(0xffffffffu, tsum, 8, 16);

            l_run[i] = l_run[i] * sc_old + tsum;

            #pragma unroll
            for (int j = 0; j < 4; j++) accO[i][j] *= sc_old;
            #pragma unroll
            for (int j = 0; j < 4; j++)
                sP[(ty * 4 + i) * 68 + tx * 4 + j] = sc[i][j];
        }
        __syncthreads();

        // O += P @ V  (kk chunked by 4 -> float4 loads both sides)
        #pragma unroll 4
        for (int kk = 0; kk < 64; kk += 4) {
            float p[4][4], vv[4][4];
            #pragma unroll
            for (int i = 0; i < 4; i++)
                *(float4*)p[i] = *(const float4*)&sP[(ty * 4 + i) * 68 + kk];
            #pragma unroll
            for (int r = 0; r < 4; r++)
                *(float4*)vv[r] = *(const float4*)&sV[(kk + r) * 68 + tx * 4];
            #pragma unroll
            for (int i = 0; i < 4; i++)
                #pragma unroll
                for (int r = 0; r < 4; r++)
                    #pragma unroll
                    for (int j = 0; j < 4; j++)
                        accO[i][j] = fmaf(p[i][r], vv[r][j], accO[i][j]);
        }
    }

    // normalize + write ctx in [b,s,D] layout
    const int b = bh >> 4, h = bh & 15;
    #pragma unroll
    for (int i = 0; i < 4; i++) {
        float inv = 1.0f / l_run[i];
        int s = q0 + ty * 4 + i;
        float4 r;
        r.x = accO[i][0] * inv;
        r.y = accO[i][1] * inv;
        r.z = accO[i][2] * inv;
        r.w = accO[i][3] * inv;
        *(float4*)&g_ctx[(size_t)(b * SEQ + s) * D_MODEL + h * HD + tx * 4] = r;
    }
}

// ---------------------------------------------------------------------------
extern "C" void kernel_launch(void* const* d_in, const int* in_sizes, int n_in,
                              void* d_out, int out_size)
{
    (void)in_sizes; (void)n_in; (void)out_size;
    const float* x  = (const float*)d_in[0];
    const float* Wq = (const float*)d_in[1];
    const float* Wk = (const float*)d_in[2];
    const float* Wv = (const float*)d_in[3];
    const float* Wo = (const float*)d_in[4];
    const float* bo = (const float*)d_in[5];
    float* out = (float*)d_out;

    cudaFuncSetAttribute(attn_kernel,
                         cudaFuncAttributeMaxDynamicSharedMemorySize, ATTN_SMEM);

    dim3 gproj(D_MODEL / 128, MTOT / 128, 3);     // 8 x 64 x 3
    gemm_qkv_kernel<<<gproj, 256>>>(x, Wq, Wk, Wv);

    dim3 gattn(SEQ / 64, BATCH * NHEADS);         // 32 x 64
    attn_kernel<<<gattn, 256, ATTN_SMEM>>>();

    dim3 gout(D_MODEL / 128, MTOT / 128);         // 8 x 64
    gemm_out_kernel<<<gout, 256>>>(Wo, bo, out);
}